// round 8
// baseline (speedup 1.0000x reference)
#include <cuda_runtime.h>
#include <math.h>

// ---------------------------------------------------------------------------
// DensityNet R8: split edge kernels (device-side src select), packed float4
// sources, ballot-segmented warp reduction, trimmed per-edge instructions.
// (R7 with the validated 5-term atan polynomial restored.)
// ---------------------------------------------------------------------------

#define NRBF 8
#define INV_HAT_WIDTH 3.5f
#define MAX_NF 65536
#define MAX_NB 8192

__device__ float4 g_srcF[MAX_NF];
__device__ float4 g_srcB[MAX_NB];
__device__ float  g_inv_support;

__global__ void prep_kernel(
    const float2* __restrict__ fluidPos,  const float* __restrict__ fluidFeat,  int nf,
    const float2* __restrict__ boundPos,  const float* __restrict__ boundFeat,  int nb,
    const float* __restrict__ support_ptr,
    float* __restrict__ out, int nout)
{
    int i = blockIdx.x * blockDim.x + threadIdx.x;
    if (i == 0) g_inv_support = __fdividef(1.0f, support_ptr[0]);
    if (i < nf) {
        float2 p = fluidPos[i];
        g_srcF[i] = make_float4(p.x, p.y, fluidFeat[i], 0.0f);
    }
    if (i < nb) {
        float2 p = boundPos[i];
        g_srcB[i] = make_float4(p.x, p.y, boundFeat[i], 0.0f);
    }
    if (i < nout) out[i] = 0.0f;
}

// atan2(y,x)/pi: octant reduction + 5-term odd minimax poly (err ~3e-6)
__device__ __forceinline__ float atan2_over_pi(float y, float x) {
    float ax = fabsf(x), ay = fabsf(y);
    float mn = fminf(ax, ay), mx = fmaxf(ax, ay);
    float t  = __fdividef(mn, mx);
    float t2 = t * t;
    float p = 0.00663147f;
    p = fmaf(p, t2, -0.0270968f);
    p = fmaf(p, t2,  0.0573382f);
    p = fmaf(p, t2, -0.1051301f);
    p = fmaf(p, t2,  0.3182684f);
    float a = t * p;
    float v = (ay > ax) ? (0.5f - a) : a;
    if (x < 0.0f) v = 1.0f - v;
    return copysignf(v, y);
}

__global__ void edge_kernel(
    const float2* __restrict__ posQ,
    int useBoundary,                    // 0 -> g_srcF, 1 -> g_srcB
    const int*    __restrict__ ei,
    const int*    __restrict__ ej,
    const float*  __restrict__ W,
    int E,
    float* __restrict__ out)
{
    const unsigned FULL = 0xffffffffu;
    const int e = blockIdx.x * blockDim.x + threadIdx.x;
    const int lane = threadIdx.x & 31;

    const float4* __restrict__ src = useBoundary ? g_srcB : g_srcF;

    float val = 0.0f;
    int qi = -1;

    if (e < E) {
        qi = __ldg(&ei[e]);
        const int sj = __ldg(&ej[e]);

        const float inv_support = g_inv_support;
        const float2 pq = posQ[qi];
        const float4 s  = src[sj];

        const float dx = (s.x - pq.x) * inv_support;
        const float dy = (s.y - pq.y) * inv_support;

        const float d2 = fmaf(dx, dx, dy * dy);
        const bool small = d2 < 1e-12f;

        const float r   = small ? 0.0f : d2 * rsqrtf(d2);
        const float ddx = small ? 1.0f : dx;
        const float ddy = small ? 0.0f : dy;

        // radial hat: p = (u+1)*3.5 = 7r
        const float pu = 7.0f * r;
        const int ia = min((int)pu, NRBF - 2);
        const float fa = fminf(pu - (float)ia, 1.0f);

        // angular hat
        const float v  = atan2_over_pi(ddy, ddx);
        const float pv = fmaf(v, INV_HAT_WIDTH, INV_HAT_WIDTH);
        const int ib = min((int)pv, NRBF - 2);
        const float fb = fminf(pv - (float)ib, 1.0f);

        const float omr  = 1.0f - r;
        const float omr2 = omr * omr;
        const float win  = fmaxf(omr2 * omr2 * fmaf(4.0f, r, 1.0f), 0.0f);

        const float* Wr0 = W + ia * NRBF + ib;
        const float* Wr1 = Wr0 + NRBF;
        const float a0 = 1.0f - fa, b0 = 1.0f - fb;
        const float w = a0 * fmaf(fb, __ldg(Wr0 + 1), b0 * __ldg(Wr0))
                      + fa * fmaf(fb, __ldg(Wr1 + 1), b0 * __ldg(Wr1));

        val = w * win * s.z;
    }

    // segmented warp suffix-sum over equal-qi runs (ballot head mask)
    const int qi_prev = __shfl_up_sync(FULL, qi, 1);
    const bool head = (lane == 0) || (qi_prev != qi);
    const unsigned hm = __ballot_sync(FULL, head);
    unsigned rest = (hm >> lane) >> 1;
    const int dist = rest ? __ffs(rest) : (32 - lane);

    #pragma unroll
    for (int off = 1; off < 32; off <<= 1) {
        float ov = __shfl_down_sync(FULL, val, off);
        if (off < dist) val += ov;
    }
    if (head && qi >= 0) atomicAdd(&out[qi], val);
}

extern "C" void kernel_launch(void* const* d_in, const int* in_sizes, int n_in,
                              void* d_out, int out_size) {
    const float2* fluidPos    = (const float2*)d_in[0];
    const float2* boundaryPos = (const float2*)d_in[1];
    const float*  fluidFeat   = (const float*)d_in[2];
    const float*  boundFeat   = (const float*)d_in[3];
    const float*  Wf          = (const float*)d_in[4];
    const float*  Wb          = (const float*)d_in[5];
    const float*  support     = (const float*)d_in[6];
    const int*    fi          = (const int*)d_in[7];
    const int*    fj          = (const int*)d_in[8];
    const int*    bf          = (const int*)d_in[9];
    const int*    bb          = (const int*)d_in[10];

    float* out = (float*)d_out;
    int nf = in_sizes[2];
    int nb = in_sizes[3];
    if (nf > MAX_NF) nf = MAX_NF;
    if (nb > MAX_NB) nb = MAX_NB;
    const int Ef = in_sizes[7];
    const int Eb = in_sizes[9];

    {
        int n = out_size;
        if (nf > n) n = nf;
        if (nb > n) n = nb;
        int threads = 256;
        int blocks = (n + threads - 1) / threads;
        prep_kernel<<<blocks, threads>>>(fluidPos, fluidFeat, nf,
                                         boundaryPos, boundFeat, nb,
                                         support, out, out_size);
    }

    const int threads = 256;
    if (Ef > 0) {
        int blocks = (Ef + threads - 1) / threads;
        edge_kernel<<<blocks, threads>>>(fluidPos, 0, fi, fj, Wf, Ef, out);
    }
    if (Eb > 0) {
        int blocks = (Eb + threads - 1) / threads;
        edge_kernel<<<blocks, threads>>>(fluidPos, 1, bf, bb, Wb, Eb, out);
    }
}

// round 9
// speedup vs baseline: 1.0832x; 1.0832x over previous
#include <cuda_runtime.h>
#include <math.h>

// ---------------------------------------------------------------------------
// DensityNet R9: fused single edge kernel (R5 structure) + R8 micro-trims.
// ---------------------------------------------------------------------------

#define NRBF 8
#define INV_HAT_WIDTH 3.5f
#define MAX_NF 65536
#define MAX_NB 8192

__device__ float4 g_srcF[MAX_NF];
__device__ float4 g_srcB[MAX_NB];
__device__ float  g_inv_support;

__global__ void prep_kernel(
    const float2* __restrict__ fluidPos,  const float* __restrict__ fluidFeat,  int nf,
    const float2* __restrict__ boundPos,  const float* __restrict__ boundFeat,  int nb,
    const float* __restrict__ support_ptr,
    float* __restrict__ out, int nout)
{
    int i = blockIdx.x * blockDim.x + threadIdx.x;
    if (i == 0) g_inv_support = __fdividef(1.0f, support_ptr[0]);
    if (i < nf) {
        float2 p = fluidPos[i];
        g_srcF[i] = make_float4(p.x, p.y, fluidFeat[i], 0.0f);
    }
    if (i < nb) {
        float2 p = boundPos[i];
        g_srcB[i] = make_float4(p.x, p.y, boundFeat[i], 0.0f);
    }
    if (i < nout) out[i] = 0.0f;
}

// atan2(y,x)/pi: octant reduction + 5-term odd minimax poly (err ~3e-6)
__device__ __forceinline__ float atan2_over_pi(float y, float x) {
    float ax = fabsf(x), ay = fabsf(y);
    float mn = fminf(ax, ay), mx = fmaxf(ax, ay);
    float t  = __fdividef(mn, mx);
    float t2 = t * t;
    float p = 0.00663147f;
    p = fmaf(p, t2, -0.0270968f);
    p = fmaf(p, t2,  0.0573382f);
    p = fmaf(p, t2, -0.1051301f);
    p = fmaf(p, t2,  0.3182684f);
    float a = t * p;
    float v = (ay > ax) ? (0.5f - a) : a;
    if (x < 0.0f) v = 1.0f - v;
    return copysignf(v, y);
}

__global__ void fused_edge_kernel(
    const float2* __restrict__ posQ,
    const int*    __restrict__ fi, const int* __restrict__ fj,
    const int*    __restrict__ bf, const int* __restrict__ bb,
    const float*  __restrict__ Wf, const float* __restrict__ Wb,
    int Ef, int Etot,
    float* __restrict__ out)
{
    const unsigned FULL = 0xffffffffu;
    const int e = blockIdx.x * blockDim.x + threadIdx.x;
    const int lane = threadIdx.x & 31;

    float val = 0.0f;
    int qi = -1;

    if (e < Etot) {
        const bool isF = (e < Ef);
        const int ee = isF ? e : (e - Ef);
        const int*    EI  = isF ? fi : bf;
        const int*    EJ  = isF ? fj : bb;
        const float4* SRC = isF ? g_srcF : g_srcB;
        const float*  WW  = isF ? Wf : Wb;

        qi = __ldg(&EI[ee]);
        const int sj = __ldg(&EJ[ee]);

        const float inv_support = g_inv_support;
        const float2 pq = posQ[qi];
        const float4 s  = SRC[sj];

        const float dx = (s.x - pq.x) * inv_support;
        const float dy = (s.y - pq.y) * inv_support;

        const float d2 = fmaf(dx, dx, dy * dy);
        const bool small = d2 < 1e-12f;

        const float r   = small ? 0.0f : d2 * rsqrtf(d2);
        const float ddx = small ? 1.0f : dx;
        const float ddy = small ? 0.0f : dy;

        // radial hat: p = (u+1)*3.5 = 7r
        const float pu = 7.0f * r;
        const int ia = min((int)pu, NRBF - 2);
        const float fa = fminf(pu - (float)ia, 1.0f);

        // angular hat
        const float v  = atan2_over_pi(ddy, ddx);
        const float pv = fmaf(v, INV_HAT_WIDTH, INV_HAT_WIDTH);
        const int ib = min((int)pv, NRBF - 2);
        const float fb = fminf(pv - (float)ib, 1.0f);

        const float omr  = 1.0f - r;
        const float omr2 = omr * omr;
        const float win  = fmaxf(omr2 * omr2 * fmaf(4.0f, r, 1.0f), 0.0f);

        const float* Wr0 = WW + ia * NRBF + ib;
        const float* Wr1 = Wr0 + NRBF;
        const float a0 = 1.0f - fa, b0 = 1.0f - fb;
        const float w = a0 * fmaf(fb, __ldg(Wr0 + 1), b0 * __ldg(Wr0))
                      + fa * fmaf(fb, __ldg(Wr1 + 1), b0 * __ldg(Wr1));

        val = w * win * s.z;
    }

    // segmented warp suffix-sum over equal-qi runs (ballot head mask)
    const int qi_prev = __shfl_up_sync(FULL, qi, 1);
    const bool head = (lane == 0) || (qi_prev != qi);
    const unsigned hm = __ballot_sync(FULL, head);
    unsigned rest = (hm >> lane) >> 1;
    const int dist = rest ? __ffs(rest) : (32 - lane);

    #pragma unroll
    for (int off = 1; off < 32; off <<= 1) {
        float ov = __shfl_down_sync(FULL, val, off);
        if (off < dist) val += ov;
    }
    if (head && qi >= 0) atomicAdd(&out[qi], val);
}

extern "C" void kernel_launch(void* const* d_in, const int* in_sizes, int n_in,
                              void* d_out, int out_size) {
    const float2* fluidPos    = (const float2*)d_in[0];
    const float2* boundaryPos = (const float2*)d_in[1];
    const float*  fluidFeat   = (const float*)d_in[2];
    const float*  boundFeat   = (const float*)d_in[3];
    const float*  Wf          = (const float*)d_in[4];
    const float*  Wb          = (const float*)d_in[5];
    const float*  support     = (const float*)d_in[6];
    const int*    fi          = (const int*)d_in[7];
    const int*    fj          = (const int*)d_in[8];
    const int*    bf          = (const int*)d_in[9];
    const int*    bb          = (const int*)d_in[10];

    float* out = (float*)d_out;
    int nf = in_sizes[2];
    int nb = in_sizes[3];
    if (nf > MAX_NF) nf = MAX_NF;
    if (nb > MAX_NB) nb = MAX_NB;
    const int Ef = in_sizes[7];
    const int Eb = in_sizes[9];
    const int Etot = Ef + Eb;

    {
        int n = out_size;
        if (nf > n) n = nf;
        if (nb > n) n = nb;
        int threads = 256;
        int blocks = (n + threads - 1) / threads;
        prep_kernel<<<blocks, threads>>>(fluidPos, fluidFeat, nf,
                                         boundaryPos, boundFeat, nb,
                                         support, out, out_size);
    }

    if (Etot > 0) {
        int threads = 256;
        int blocks = (Etot + threads - 1) / threads;
        fused_edge_kernel<<<blocks, threads>>>(
            fluidPos, fi, fj, bf, bb, Wf, Wb, Ef, Etot, out);
    }
}

// round 10
// speedup vs baseline: 1.1442x; 1.0563x over previous
#include <cuda_runtime.h>
#include <math.h>

// ---------------------------------------------------------------------------
// DensityNet R10: 2 edges/thread with pair-merge + ballot-segmented scan,
// paired float2 W tables, packed float4 sources.
// ---------------------------------------------------------------------------

#define NRBF 8
#define INV_HAT_WIDTH 3.5f
#define MAX_NF 65536
#define MAX_NB 8192

__device__ float4 g_srcF[MAX_NF];
__device__ float4 g_srcB[MAX_NB];
__device__ float2 g_WfPair[NRBF * NRBF];
__device__ float2 g_WbPair[NRBF * NRBF];
__device__ float  g_inv_support;

__global__ void prep_kernel(
    const float2* __restrict__ fluidPos,  const float* __restrict__ fluidFeat,  int nf,
    const float2* __restrict__ boundPos,  const float* __restrict__ boundFeat,  int nb,
    const float* __restrict__ Wf, const float* __restrict__ Wb,
    const float* __restrict__ support_ptr,
    float* __restrict__ out, int nout)
{
    int i = blockIdx.x * blockDim.x + threadIdx.x;
    if (i == 0) g_inv_support = __fdividef(1.0f, support_ptr[0]);
    if (i < NRBF * NRBF) {
        int j = i & (NRBF - 1);
        float bump = (j < NRBF - 1) ? 1.0f : 0.0f;  // j=7 never used as left idx
        g_WfPair[i] = make_float2(Wf[i], bump * Wf[min(i + 1, NRBF*NRBF - 1)]);
        g_WbPair[i] = make_float2(Wb[i], bump * Wb[min(i + 1, NRBF*NRBF - 1)]);
    }
    if (i < nf) {
        float2 p = fluidPos[i];
        g_srcF[i] = make_float4(p.x, p.y, fluidFeat[i], 0.0f);
    }
    if (i < nb) {
        float2 p = boundPos[i];
        g_srcB[i] = make_float4(p.x, p.y, boundFeat[i], 0.0f);
    }
    if (i < nout) out[i] = 0.0f;
}

// atan2(y,x)/pi: octant reduction + 5-term odd minimax poly (err ~3e-6)
__device__ __forceinline__ float atan2_over_pi(float y, float x) {
    float ax = fabsf(x), ay = fabsf(y);
    float mn = fminf(ax, ay), mx = fmaxf(ax, ay);
    float t  = __fdividef(mn, mx);
    float t2 = t * t;
    float p = 0.00663147f;
    p = fmaf(p, t2, -0.0270968f);
    p = fmaf(p, t2,  0.0573382f);
    p = fmaf(p, t2, -0.1051301f);
    p = fmaf(p, t2,  0.3182684f);
    float a = t * p;
    float v = (ay > ax) ? (0.5f - a) : a;
    if (x < 0.0f) v = 1.0f - v;
    return copysignf(v, y);
}

__device__ __forceinline__ float edge_val(
    float2 pq, float4 s, float inv_support, const float2* __restrict__ WP)
{
    const float dx = (s.x - pq.x) * inv_support;
    const float dy = (s.y - pq.y) * inv_support;

    const float d2 = fmaf(dx, dx, dy * dy);
    const bool small = d2 < 1e-12f;

    const float r   = small ? 0.0f : d2 * rsqrtf(d2);
    const float ddx = small ? 1.0f : dx;
    const float ddy = small ? 0.0f : dy;

    const float pu = 7.0f * r;                       // radial hat: (u+1)*3.5
    const int ia = min((int)pu, NRBF - 2);
    const float fa = fminf(pu - (float)ia, 1.0f);

    const float v  = atan2_over_pi(ddy, ddx);
    const float pv = fmaf(v, INV_HAT_WIDTH, INV_HAT_WIDTH);
    const int ib = min((int)pv, NRBF - 2);
    const float fb = fminf(pv - (float)ib, 1.0f);

    const float omr  = 1.0f - r;
    const float omr2 = omr * omr;
    const float win  = fmaxf(omr2 * omr2 * fmaf(4.0f, r, 1.0f), 0.0f);

    const float2 w0 = __ldg(&WP[ia * NRBF + ib]);
    const float2 w1 = __ldg(&WP[(ia + 1) * NRBF + ib]);
    const float a0 = 1.0f - fa, b0 = 1.0f - fb;
    const float w = a0 * fmaf(fb, w0.y, b0 * w0.x)
                  + fa * fmaf(fb, w1.y, b0 * w1.x);

    return w * win * s.z;
}

__global__ void fused_edge_kernel(
    const float2* __restrict__ posQ,
    const int*    __restrict__ fi, const int* __restrict__ fj,
    const int*    __restrict__ bf, const int* __restrict__ bb,
    int Pf, int Ptot, int Ef, int Eb,
    float* __restrict__ out)
{
    const unsigned FULL = 0xffffffffu;
    const int t = blockIdx.x * blockDim.x + threadIdx.x;
    const int lane = threadIdx.x & 31;

    float val = 0.0f;   // value carried into the scan (last edge of pair)
    int qi = -1;        // qi carried into the scan

    if (t < Ptot) {
        const bool isF = (t < Pf);
        const int pp = isF ? t : (t - Pf);
        const int E  = isF ? Ef : Eb;
        const int*    EI  = isF ? fi : bf;
        const int*    EJ  = isF ? fj : bb;
        const float4* SRC = isF ? g_srcF : g_srcB;
        const float2* WP  = isF ? g_WfPair : g_WbPair;

        const float inv_support = g_inv_support;
        const int e0 = 2 * pp;
        const bool has1 = (e0 + 1) < E;

        int qi0, qi1, sj0, sj1;
        if (has1) {
            int2 q2 = __ldg((const int2*)EI + pp);
            int2 s2 = __ldg((const int2*)EJ + pp);
            qi0 = q2.x; qi1 = q2.y; sj0 = s2.x; sj1 = s2.y;
        } else {
            qi0 = __ldg(&EI[e0]); sj0 = __ldg(&EJ[e0]);
            qi1 = qi0; sj1 = sj0;
        }

        const float2 pq0 = posQ[qi0];
        const float4 s0  = SRC[sj0];
        float v0 = edge_val(pq0, s0, inv_support, WP);

        float v1 = 0.0f;
        if (has1) {
            const float2 pq1 = posQ[qi1];
            const float4 s1  = SRC[sj1];
            v1 = edge_val(pq1, s1, inv_support, WP);
        }

        if (qi0 == qi1) {
            val = v0 + v1;
            qi = qi0;
        } else {
            // qi0's run ends inside this thread; flush it directly.
            atomicAdd(&out[qi0], v0);
            val = v1;
            qi = qi1;
        }
    }

    // segmented warp suffix-sum over equal-qi runs (ballot head mask)
    const int qi_prev = __shfl_up_sync(FULL, qi, 1);
    const bool head = (lane == 0) || (qi_prev != qi);
    const unsigned hm = __ballot_sync(FULL, head);
    unsigned rest = (hm >> lane) >> 1;
    const int dist = rest ? __ffs(rest) : (32 - lane);

    #pragma unroll
    for (int off = 1; off < 32; off <<= 1) {
        float ov = __shfl_down_sync(FULL, val, off);
        if (off < dist) val += ov;
    }
    if (head && qi >= 0) atomicAdd(&out[qi], val);
}

extern "C" void kernel_launch(void* const* d_in, const int* in_sizes, int n_in,
                              void* d_out, int out_size) {
    const float2* fluidPos    = (const float2*)d_in[0];
    const float2* boundaryPos = (const float2*)d_in[1];
    const float*  fluidFeat   = (const float*)d_in[2];
    const float*  boundFeat   = (const float*)d_in[3];
    const float*  Wf          = (const float*)d_in[4];
    const float*  Wb          = (const float*)d_in[5];
    const float*  support     = (const float*)d_in[6];
    const int*    fi          = (const int*)d_in[7];
    const int*    fj          = (const int*)d_in[8];
    const int*    bf          = (const int*)d_in[9];
    const int*    bb          = (const int*)d_in[10];

    float* out = (float*)d_out;
    int nf = in_sizes[2];
    int nb = in_sizes[3];
    if (nf > MAX_NF) nf = MAX_NF;
    if (nb > MAX_NB) nb = MAX_NB;
    const int Ef = in_sizes[7];
    const int Eb = in_sizes[9];
    const int Pf = (Ef + 1) / 2;
    const int Pb = (Eb + 1) / 2;
    const int Ptot = Pf + Pb;

    {
        int n = out_size;
        if (nf > n) n = nf;
        if (nb > n) n = nb;
        int threads = 256;
        int blocks = (n + threads - 1) / threads;
        prep_kernel<<<blocks, threads>>>(fluidPos, fluidFeat, nf,
                                         boundaryPos, boundFeat, nb,
                                         Wf, Wb, support, out, out_size);
    }

    if (Ptot > 0) {
        int threads = 256;
        int blocks = (Ptot + threads - 1) / threads;
        fused_edge_kernel<<<blocks, threads>>>(
            fluidPos, fi, fj, bf, bb, Pf, Ptot, Ef, Eb, out);
    }
}